// round 8
// baseline (speedup 1.0000x reference)
#include <cuda_runtime.h>

#define HH 512
#define WW 512
#define NIMG 24            // 8 * 3 planes
#define KS 121
#define MEANR 60
#define NSTEP 61           // pair-steps = 122 taps (121 real + 1 zero)
#define NCHUNK 56          // 7 chunks of 8, then 5-step tail
#define PITCH 66           // floats per pair-row in shared (33 u64, conflict-free)

typedef unsigned long long u64;

__device__ float g_tmp[NIMG * HH * WW];

// packed fp32x2 fma: a.xy += b.xy * c.xy  (Blackwell FFMA2, PTX-only)
__device__ __forceinline__ void ffma2(u64& a, u64 b, u64 c) {
    asm("fma.rn.f32x2 %0, %1, %2, %0;" : "+l"(a) : "l"(b), "l"(c));
}
__device__ __forceinline__ float2 u2f(u64 v) {
    float2 r;
    asm("mov.b64 {%0, %1}, %2;" : "=f"(r.x), "=f"(r.y) : "l"(v));
    return r;
}

// Per-block weight prologue: duplicated-pair weights sw2[t] = (w[t], w[t]).
// sw2 has 128 entries = 64 pair-steps; steps >= NSTEP are zero (safe prefetch).
__device__ __forceinline__ void make_weights(const float* sigma, u64* sw2,
                                             float* sred, int tid) {
    float e = 0.0f;
    if (tid < 128) {
        float s = sigma[0] * 8.0f + 16.0f;
        float d = (float)(tid - MEANR);
        e = (tid < KS) ? expf(-(d * d) / (2.0f * s * s)) : 0.0f;
        sred[tid] = e;
    }
    __syncthreads();
    if (tid < 32) {
        float s4 = sred[tid] + sred[tid + 32] + sred[tid + 64] + sred[tid + 96];
        #pragma unroll
        for (int off = 16; off > 0; off >>= 1)
            s4 += __shfl_xor_sync(0xffffffffu, s4, off);
        if (tid == 0) sred[0] = s4;
    }
    __syncthreads();
    if (tid < 128) {
        float wv = e / sred[0];          // zero for tid >= KS
        float2 p; p.x = wv; p.y = wv;
        sw2[tid] = *(u64*)&p;
    }
}

// Core tap loop, software-pipelined: weights and ring value for step s+1 are
// loaded before step s's FMA block -> every LDS gets a full FMA block of slack.
__device__ __forceinline__ void tap_loop(const u64* __restrict__ base,
                                         const u64* __restrict__ sw2,
                                         u64* accE, u64* accQ, u64& accQ8) {
    const ulonglong2* wp = (const ulonglong2*)sw2;   // wp[s] = (we, wo), 16B
    u64 P[8];
    #pragma unroll
    for (int m = 0; m < 8; m++) { P[m] = base[m * 33]; accE[m] = 0ull; accQ[m] = 0ull; }
    accQ8 = 0ull;

    ulonglong2 w2 = wp[0];
    u64 Pn = base[8 * 33];

    #pragma unroll 1
    for (int ss = 0; ss < NCHUNK; ss += 8) {
        const u64* bp = base + ss * 33;
        const ulonglong2* wpp = wp + ss;
        #pragma unroll
        for (int u = 0; u < 8; u++) {
            ulonglong2 w2n = wpp[u + 1];            // prefetch step s+1 weights
            u64 Pn2 = bp[(u + 9) * 33];             // prefetch step s+1 ring value
            #pragma unroll
            for (int m = 0; m < 8; m++) {
                ffma2(accE[m], w2.x, P[(u + m) & 7]);
                ffma2(accQ[m], w2.y, P[(u + m) & 7]);
            }
            ffma2(accQ8, w2.y, Pn);
            P[u & 7] = Pn;
            w2 = w2n;
            Pn = Pn2;
        }
    }
    // tail: steps 56..60 (phase consistent: 56 % 8 == 0).  Prefetch indices
    // stay in bounds: wp[61] is a zero pair, base row <= 127.
    #pragma unroll
    for (int s = NCHUNK; s < NSTEP; s++) {
        ulonglong2 w2n = wp[s + 1];
        u64 Pn2 = base[(s + 9) * 33];
        #pragma unroll
        for (int m = 0; m < 8; m++) {
            ffma2(accE[m], w2.x, P[(s + m) & 7]);
            ffma2(accQ[m], w2.y, P[(s + m) & 7]);
        }
        ffma2(accQ8, w2.y, Pn);
        P[s & 7] = Pn;
        w2 = w2n;
        Pn = Pn2;
    }
}

// ---------------------------------------------------------------------------
// Horizontal pass: x -> g_tmp.  Block = 32 rows x 128 x-outputs.
// Warp w: x-columns [X0+16w .. +15], lanes = 32 rows.
// Shared sh[pair p][row r] (pitch 66 floats): pair p covers x = X0-64+2p.
// ---------------------------------------------------------------------------
__global__ __launch_bounds__(256, 3) void hpass_kernel(const float* __restrict__ x,
                                                       const float* __restrict__ sigma) {
    __shared__ __align__(16) u64 sw2[128];
    __shared__ float sred[128];
    __shared__ float shf[128 * PITCH];     // 33792 B

    int tid = threadIdx.x;
    int X0 = blockIdx.x * 128;
    int r0 = blockIdx.y * 32;

    // load 256 x-inputs (clamped) x 32 rows; coalesced along x
    {
        int xo = tid;
        int src = min(max(X0 - 64 + xo, 0), WW - 1);
        int sidx = (xo >> 1) * PITCH + (xo & 1);
        const float* xp = x + (long)r0 * WW + src;
        #pragma unroll 4
        for (int r = 0; r < 32; r++)
            shf[sidx + 2 * r] = xp[(long)r * WW];
    }
    make_weights(sigma, sw2, sred, tid);
    __syncthreads();

    int w = tid >> 5;
    int l = tid & 31;
    const u64* base = (const u64*)shf + (8 * w + 2) * 33 + l;

    u64 accE[8], accQ[8], accQ8;
    tap_loop(base, sw2, accE, accQ, accQ8);

    float2* orow = (float2*)(g_tmp + (long)(r0 + l) * WW + X0 + 16 * w);
    #pragma unroll
    for (int m = 0; m < 8; m++) {
        float2 E = u2f(accE[m]);
        float2 Q = u2f(accQ[m]);
        float qn = (m < 7) ? u2f(accQ[m + 1]).x : u2f(accQ8).x;
        orow[m] = make_float2(E.x + Q.y, E.y + qn);
    }
}

// ---------------------------------------------------------------------------
// Vertical pass: g_tmp -> out.  Block = 32 cols x 128 y-outputs.
// Warp w: y-rows [Y0+16w .. +15], lanes = 32 cols.
// Shared sh[ypair p][col c] (pitch 66): pair p covers y = Y0-64+2p (clamped).
// ---------------------------------------------------------------------------
__global__ __launch_bounds__(256, 3) void vpass_kernel(float* __restrict__ out,
                                                       const float* __restrict__ sigma) {
    __shared__ __align__(16) u64 sw2[128];
    __shared__ float sred[128];
    __shared__ float shf[128 * PITCH];

    int tid = threadIdx.x;
    int img  = blockIdx.z;
    int col0 = blockIdx.x * 32;
    int Y0   = blockIdx.y * 128;
    const float* tp = g_tmp + (long)img * HH * WW + col0;

    // load 256 y-rows (clamped) x 32 cols; coalesced along cols
    {
        int cc = tid & 31;
        int wy = tid >> 5;
        #pragma unroll 4
        for (int k = 0; k < 32; k++) {
            int yy = k * 8 + wy;
            int sy = min(max(Y0 - 64 + yy, 0), HH - 1);
            shf[(yy >> 1) * PITCH + 2 * cc + (yy & 1)] = tp[(long)sy * WW + cc];
        }
    }
    make_weights(sigma, sw2, sred, tid);
    __syncthreads();

    int w = tid >> 5;
    int c = tid & 31;
    const u64* base = (const u64*)shf + (8 * w + 2) * 33 + c;

    u64 accE[8], accQ[8], accQ8;
    tap_loop(base, sw2, accE, accQ, accQ8);

    float* op = out + (long)img * HH * WW + (long)(Y0 + 16 * w) * WW + col0 + c;
    #pragma unroll
    for (int m = 0; m < 8; m++) {
        float2 E = u2f(accE[m]);
        float2 Q = u2f(accQ[m]);
        float qn = (m < 7) ? u2f(accQ[m + 1]).x : u2f(accQ8).x;
        op[(long)(2 * m)     * WW] = E.x + Q.y;
        op[(long)(2 * m + 1) * WW] = E.y + qn;
    }
}

// ---------------------------------------------------------------------------
extern "C" void kernel_launch(void* const* d_in, const int* in_sizes, int n_in,
                              void* d_out, int out_size) {
    const float* x     = (const float*)d_in[0];
    const float* sigma = (const float*)d_in[1];
    float* out = (float*)d_out;

    dim3 hgrid(WW / 128, (NIMG * HH) / 32);      // 4 x 384 = 1536
    hpass_kernel<<<hgrid, 256>>>(x, sigma);

    dim3 vgrid(WW / 32, HH / 128, NIMG);         // 16 x 4 x 24 = 1536
    vpass_kernel<<<vgrid, 256>>>(out, sigma);
}

// round 11
// speedup vs baseline: 1.8136x; 1.8136x over previous
#include <cuda_runtime.h>
#include <cuda_bf16.h>
#include <cstdint>

#define NLINES 12288       // 24 planes * 512 lines
#define LW 512
#define KS 121
#define PB 528             // B row pitch in bytes (256 bf16 + 16B pad)

// dynamic smem layout
#define SM_BH 0            // B_hi [64 n][256 k] bf16, pitch PB: 33792 B
#define SM_BL 33792        // B_lo: 33792 B
#define SM_TBH 67584       // u32[176] hi weight-pair table (wp[i]=(w[i],w[i+1]), i=idx-16)
#define SM_TBL 68288       // u32[176] lo table
#define SM_SRED 68992      // float[128] reduction scratch
#define SM_TOTAL 69504

__device__ float g_tmp[NLINES * LW];

static __device__ __forceinline__ void mma_bf16(float* c, uint32_t a0, uint32_t a1,
                                                uint32_t a2, uint32_t a3,
                                                uint32_t b0, uint32_t b1) {
    asm volatile(
        "mma.sync.aligned.m16n8k16.row.col.f32.bf16.bf16.f32 "
        "{%0,%1,%2,%3}, {%4,%5,%6,%7}, {%8,%9}, {%0,%1,%2,%3};"
        : "+f"(c[0]), "+f"(c[1]), "+f"(c[2]), "+f"(c[3])
        : "r"(a0), "r"(a1), "r"(a2), "r"(a3), "r"(b0), "r"(b1));
}

static __device__ __forceinline__ uint32_t pack_bf2(float lo, float hi) {
    __nv_bfloat162 h;
    h.x = __float2bfloat16(lo);
    h.y = __float2bfloat16(hi);
    return *(uint32_t*)&h;
}

// ---------------------------------------------------------------------------
// One separable-blur pass as a banded GEMM on tensor cores (mma.sync bf16,
// 3-term hi/lo error split, fp32 accumulate).
// D[m=128 outs, n=64 lines] = A[m,k] * B[n,k]^T,  A[m,k] = w[k-m] (Toeplitz,
// generated from a pair table, never materialized).  Output written
// plane-transposed; two passes compose to the correct layout.
// ---------------------------------------------------------------------------
__global__ __launch_bounds__(256)
void blur_pass(const float* __restrict__ x, float* __restrict__ outp,
               const float* __restrict__ sigma, int first) {
    extern __shared__ char smem[];
    int tid = threadIdx.x;
    int ib = blockIdx.x;             // 0..3: output block along the line
    int L0 = blockIdx.y * 64;        // first line of the 64-line tile

    const float* in = first ? x : (const float*)g_tmp;
    float* out = first ? (float*)g_tmp : outp;

    // ---- B build: thread = (k-pair k2 = tid&127, line-half = tid>>7) ----
    {
        int k2 = tid & 127, half = tid >> 7;
        int gx0 = min(max(ib * 128 - 60 + 2 * k2, 0), LW - 1);
        int gx1 = min(max(ib * 128 - 60 + 2 * k2 + 1, 0), LW - 1);
        const float* ip0 = in + (long)(L0 + half * 32) * LW + gx0;
        const float* ip1 = in + (long)(L0 + half * 32) * LW + gx1;
        char* bh = smem + SM_BH + half * 32 * PB + k2 * 4;
        char* bl = smem + SM_BL + half * 32 * PB + k2 * 4;
        #pragma unroll 4
        for (int n = 0; n < 32; n++) {
            float v0 = ip0[(long)n * LW];
            float v1 = ip1[(long)n * LW];
            float h0 = __bfloat162float(__float2bfloat16(v0));
            float h1 = __bfloat162float(__float2bfloat16(v1));
            *(uint32_t*)(bh + n * PB) = pack_bf2(v0, v1);
            *(uint32_t*)(bl + n * PB) = pack_bf2(v0 - h0, v1 - h1);
        }
    }

    // ---- weights + pair tables ----
    {
        float* sred = (float*)(smem + SM_SRED);
        float e = 0.0f;
        if (tid < 128) {
            float s = sigma[0] * 8.0f + 16.0f;
            float d = (float)(tid - 60);
            e = (tid < KS) ? expf(-(d * d) / (2.0f * s * s)) : 0.0f;
            sred[tid] = e;
        }
        __syncthreads();
        float* wf = (float*)(smem + SM_SRED);   // reuse as w[] after reduction
        if (tid < 32) {
            float s4 = sred[tid] + sred[tid + 32] + sred[tid + 64] + sred[tid + 96];
            #pragma unroll
            for (int off = 16; off > 0; off >>= 1)
                s4 += __shfl_xor_sync(0xffffffffu, s4, off);
            if (tid == 0) sred[0] = s4;
        }
        __syncthreads();
        float sum = wf[0];
        __syncthreads();                         // sum read before overwrite
        if (tid < 128) wf[tid] = e / sum;        // wf[121..127] = 0
        __syncthreads();
        if (tid < 176) {
            int i = tid - 16;
            float w0 = ((unsigned)i < 128u) ? wf[i] : 0.0f;
            float w1 = ((unsigned)(i + 1) < 128u) ? wf[i + 1] : 0.0f;
            float h0 = __bfloat162float(__float2bfloat16(w0));
            float h1 = __bfloat162float(__float2bfloat16(w1));
            ((uint32_t*)(smem + SM_TBH))[tid] = pack_bf2(w0, w1);
            ((uint32_t*)(smem + SM_TBL))[tid] = pack_bf2(w0 - h0, w1 - h1);
        }
    }
    __syncthreads();

    // ---- mainloop: warp = 16-row m-strip; 9 active k-chunks (band) ----
    int wid = tid >> 5, lane = tid & 31;
    int g = lane >> 2, t = lane & 3;
    int m0 = wid * 16;

    float c[8][4];
    #pragma unroll
    for (int j = 0; j < 8; j++)
        #pragma unroll
        for (int r = 0; r < 4; r++) c[j][r] = 0.0f;

    const uint32_t* tbh = (const uint32_t*)(smem + SM_TBH);
    const uint32_t* tbl = (const uint32_t*)(smem + SM_TBL);
    // B fragment base: row n = 8j+g, k-offset k0+2t (b0) / +8 (b1)
    const char* bhbase = smem + SM_BH + (8 * 0 + g) * PB;   // + j*8*PB later
    const char* blbase = smem + SM_BL + g * PB;

    #pragma unroll 1
    for (int q = 0; q < 9; q++) {
        int k0 = m0 + 16 * q;                 // global k-chunk base
        int di = 16 * q + 2 * t - g + 16;     // table index for a0/a3
        uint32_t ah0 = tbh[di], ah1 = tbh[di - 8], ah2 = tbh[di + 8];
        uint32_t al0 = tbl[di], al1 = tbl[di - 8], al2 = tbl[di + 8];

        uint32_t b[8][2];
        const char* bp = bhbase + (k0 + 2 * t) * 2;
        #pragma unroll
        for (int j = 0; j < 8; j++) {
            b[j][0] = *(const uint32_t*)(bp + j * 8 * PB);
            b[j][1] = *(const uint32_t*)(bp + j * 8 * PB + 16);
        }
        #pragma unroll
        for (int j = 0; j < 8; j++)
            mma_bf16(c[j], ah0, ah1, ah2, ah0, b[j][0], b[j][1]);   // Ah*Bh
        #pragma unroll
        for (int j = 0; j < 8; j++)
            mma_bf16(c[j], al0, al1, al2, al0, b[j][0], b[j][1]);   // Al*Bh

        const char* lp = blbase + (k0 + 2 * t) * 2;
        #pragma unroll
        for (int j = 0; j < 8; j++) {
            b[j][0] = *(const uint32_t*)(lp + j * 8 * PB);
            b[j][1] = *(const uint32_t*)(lp + j * 8 * PB + 16);
        }
        #pragma unroll
        for (int j = 0; j < 8; j++)
            mma_bf16(c[j], ah0, ah1, ah2, ah0, b[j][0], b[j][1]);   // Ah*Bl
    }

    // ---- epilogue: D[m][n] -> plane-transposed store ----
    {
        int p = L0 >> 9;                // plane
        int lp0 = L0 & 511;             // line within plane
        long row = (long)(p * 512 + ib * 128 + m0 + g);
        float* o0 = out + row * 512 + lp0;
        float* o1 = o0 + 8 * 512;       // row +8
        #pragma unroll
        for (int j = 0; j < 8; j++) {
            int n = 8 * j + 2 * t;
            *(float2*)(o0 + n) = make_float2(c[j][0], c[j][1]);
            *(float2*)(o1 + n) = make_float2(c[j][2], c[j][3]);
        }
    }
}

// ---------------------------------------------------------------------------
extern "C" void kernel_launch(void* const* d_in, const int* in_sizes, int n_in,
                              void* d_out, int out_size) {
    const float* x     = (const float*)d_in[0];
    const float* sigma = (const float*)d_in[1];
    float* out = (float*)d_out;

    cudaFuncSetAttribute(blur_pass, cudaFuncAttributeMaxDynamicSharedMemorySize,
                         SM_TOTAL);

    dim3 grid(LW / 128, NLINES / 64);   // 4 x 192 = 768 CTAs
    blur_pass<<<grid, 256, SM_TOTAL>>>(x, out, sigma, 1);   // x -> g_tmp (T)
    blur_pass<<<grid, 256, SM_TOTAL>>>(x, out, sigma, 0);   // g_tmp -> out (T back)
}